// round 15
// baseline (speedup 1.0000x reference)
#include <cuda_runtime.h>
#include <math.h>

#define NSTACK 12
#define ZEROOFF 0.001f
#define EPSV 1e-8f
#define CREC 40      // staged record: a[0:12] c[12:24] q[24:36] pop[36] sq[37] pad->40
#define CS 32        // chunk size
#define NCH 8        // chunks (T/CS)
#define KB2 8        // k2 blocks per batch
#define BFIX 32      // batch count (fixed shape)

// Fixed shapes (B=32, T=256, V=2048).
__device__ float g_interp[32 * 256];
__device__ float g_partd[32 * KB2 * 256];
__device__ float g_partn[32 * KB2 * 256];
__device__ float g_partsp[KB2];
__device__ float g_popT[256 * 32];                    // pops transposed [t][b]
__device__ float g_vT[257 * NSTACK * 32];             // pointer states [t][n][b], t=0..T
__device__ __align__(16) float g_achunk[32 * NCH * NSTACK];
__device__ __align__(16) float g_W[32 * NCH * 2048 * NSTACK];  // [b][ch][col][n]

typedef unsigned long long ull;

__device__ __forceinline__ ull pack2(float lo, float hi) {
    ull r;
    asm("mov.b64 %0, {%1, %2};" : "=l"(r) : "f"(lo), "f"(hi));
    return r;
}
__device__ __forceinline__ void unpack2(ull v, float& lo, float& hi) {
    asm("mov.b64 {%0, %1}, %2;" : "=f"(lo), "=f"(hi) : "l"(v));
}
__device__ __forceinline__ ull fma2(ull a, ull b, ull c) {
    ull d;
    asm("fma.rn.f32x2 %0, %1, %2, %3;" : "=l"(d) : "l"(a), "l"(b), "l"(c));
    return d;
}
__device__ __forceinline__ ull mul2(ull a, ull b) {
    ull d;
    asm("mul.rn.f32x2 %0, %1, %2;" : "=l"(d) : "l"(a), "l"(b));
    return d;
}

// ---------------------------------------------------------------------------
// K1: interp[b,t] = cos(latch_enable, x[b,t]).  One WARP per row, MLP=8.
// ---------------------------------------------------------------------------
__global__ void k1_interp(const float* __restrict__ x, const float* __restrict__ le, int V) {
    int row = blockIdx.x * 8 + (threadIdx.x >> 5);
    int lane = threadIdx.x & 31;
    const float4* xp = (const float4*)(x + (size_t)row * V);
    const float4* le4 = (const float4*)le;
    float d = 0.f, n = 0.f, m = 0.f;
    for (int i0 = lane; i0 < V / 4; i0 += 128) {
        float4 xv[4], l[4];
        #pragma unroll
        for (int j = 0; j < 4; j++) { xv[j] = xp[i0 + 32 * j]; l[j] = le4[i0 + 32 * j]; }
        #pragma unroll
        for (int j = 0; j < 4; j++) {
            d += l[j].x * xv[j].x + l[j].y * xv[j].y + l[j].z * xv[j].z + l[j].w * xv[j].w;
            n += xv[j].x * xv[j].x + xv[j].y * xv[j].y + xv[j].z * xv[j].z + xv[j].w * xv[j].w;
            m += l[j].x * l[j].x + l[j].y * l[j].y + l[j].z * l[j].z + l[j].w * l[j].w;
        }
    }
    #pragma unroll
    for (int o = 16; o > 0; o >>= 1) {
        d += __shfl_xor_sync(0xffffffffu, d, o);
        n += __shfl_xor_sync(0xffffffffu, n, o);
        m += __shfl_xor_sync(0xffffffffu, m, o);
    }
    if (lane == 0) {
        float nle = fmaxf(sqrtf(m), EPSV);
        float nx = fmaxf(sqrtf(n), EPSV);
        g_interp[row] = d / (nle * nx);
    }
}

// ---------------------------------------------------------------------------
// K2: latch scan + fused pop partials. grid (KB2, B), block 128, float2/thread.
// ---------------------------------------------------------------------------
__global__ void k2_latch(const float* __restrict__ x, const float* __restrict__ latch0,
                         const float* __restrict__ sp, float* __restrict__ latches,
                         int T, int V) {
    __shared__ float s_i[256];
    __shared__ float s_wd[256][4];
    __shared__ float s_wn[256][4];
    __shared__ float s_sp[4];
    int b = blockIdx.y;
    int tid = threadIdx.x;
    int lane = tid & 31;
    int w = tid >> 5;
    int v2 = blockIdx.x * blockDim.x + tid;
    int stride2 = V >> 1;

    for (int t = tid; t < T; t += blockDim.x) s_i[t] = g_interp[b * T + t];
    __syncthreads();

    float2 sp2 = ((const float2*)sp)[v2];
    float2 latch = ((const float2*)(latch0 + (size_t)b * V))[v2];
    const float2* xp = (const float2*)(x + (size_t)b * T * V) + v2;
    float2* lp = (float2*)(latches + (size_t)b * T * V) + v2;

    {
        float d = sp2.x * latch.x + sp2.y * latch.y;
        float n = latch.x * latch.x + latch.y * latch.y;
        float m = sp2.x * sp2.x + sp2.y * sp2.y;
        #pragma unroll
        for (int o = 16; o > 0; o >>= 1) {
            d += __shfl_xor_sync(0xffffffffu, d, o);
            n += __shfl_xor_sync(0xffffffffu, n, o);
            m += __shfl_xor_sync(0xffffffffu, m, o);
        }
        if (lane == 0) { s_wd[0][w] = d; s_wn[0][w] = n; s_sp[w] = m; }
    }

    for (int t0 = 0; t0 < T; t0 += 8) {
        float2 xs[8];
        #pragma unroll
        for (int j = 0; j < 8; j++) xs[j] = xp[(size_t)(t0 + j) * stride2];
        float d8[8], n8[8];
        #pragma unroll
        for (int j = 0; j < 8; j++) {
            float i = s_i[t0 + j];
            latch.x = fmaf(i, xs[j].x - latch.x, latch.x);
            latch.y = fmaf(i, xs[j].y - latch.y, latch.y);
            lp[(size_t)(t0 + j) * stride2] = latch;
            d8[j] = sp2.x * latch.x + sp2.y * latch.y;
            n8[j] = latch.x * latch.x + latch.y * latch.y;
        }
        #pragma unroll
        for (int o = 16; o > 0; o >>= 1) {
            #pragma unroll
            for (int j = 0; j < 8; j++) {
                d8[j] += __shfl_xor_sync(0xffffffffu, d8[j], o);
                n8[j] += __shfl_xor_sync(0xffffffffu, n8[j], o);
            }
        }
        if (lane == 0) {
            #pragma unroll
            for (int j = 0; j < 8; j++) {
                int t = t0 + j;
                if (t + 1 < T) { s_wd[t + 1][w] = d8[j]; s_wn[t + 1][w] = n8[j]; }
            }
        }
    }
    __syncthreads();
    int pbase = (b * KB2 + blockIdx.x) * T;
    for (int t = tid; t < T; t += blockDim.x) {
        g_partd[pbase + t] = s_wd[t][0] + s_wd[t][1] + s_wd[t][2] + s_wd[t][3];
        g_partn[pbase + t] = s_wn[t][0] + s_wn[t][1] + s_wn[t][2] + s_wn[t][3];
    }
    if (b == 0 && tid == 0)
        g_partsp[blockIdx.x] = s_sp[0] + s_sp[1] + s_sp[2] + s_sp[3];
}

// ---------------------------------------------------------------------------
// K3b: finalize pop[b,t] = elu(cos); write pops output + transposed copy.
// ---------------------------------------------------------------------------
__global__ void k3b_pops(float* __restrict__ pops, int T) {
    int bt = blockIdx.x * blockDim.x + threadIdx.x;
    int b = bt / T;
    int t = bt - b * T;
    float d = 0.f, n = 0.f;
    #pragma unroll
    for (int blk = 0; blk < KB2; blk++) {
        d += g_partd[(b * KB2 + blk) * T + t];
        n += g_partn[(b * KB2 + blk) * T + t];
    }
    float sp2 = 0.f;
    #pragma unroll
    for (int blk = 0; blk < KB2; blk++) sp2 += g_partsp[blk];
    float nsp = fmaxf(sqrtf(sp2), EPSV);
    float nl = fmaxf(sqrtf(n), EPSV);
    float c = d / (nsp * nl);
    float p = (c > 0.0f) ? c : expm1f(c);
    pops[bt] = p;
    g_popT[t * BFIX + b] = p;
}

// ---------------------------------------------------------------------------
// K4: pointer scan, lane-per-batch, stores ONLY the pointer state v (12 STG
// per step). One warp, all 32 batches. Aacc moved to k5a.
// ---------------------------------------------------------------------------
__global__ void k4_scan(const float* __restrict__ sharp_ptr, int T) {
    __shared__ float s_pop[256 * BFIX];   // [t][b], 32KB
    int lane = threadIdx.x;               // = batch b

    {
        const float4* src = (const float4*)g_popT;
        float4* dst = (float4*)s_pop;
        for (int i = lane; i < T * BFIX / 4; i += 32) dst[i] = src[i];
    }
    __syncwarp();

    float sharp = sharp_ptr[0];
    bool fast5 = (sharp == 5.0f);

    float v[NSTACK];
    #pragma unroll
    for (int n = 0; n < NSTACK; n++) v[n] = 0.f;
    v[0] = 1.0f;

    for (int t = 0; t < T; t++) {
        float* vf = g_vT + (size_t)t * NSTACK * BFIX + lane;
        #pragma unroll
        for (int n = 0; n < NSTACK; n++) vf[n * BFIX] = v[n];

        float pop = s_pop[t * BFIX + lane];
        float push = 1.0f - pop;

        float pw[NSTACK];
        #pragma unroll
        for (int n = 0; n < NSTACK; n++) {
            float vp = v[(n + NSTACK - 1) % NSTACK];
            float vn = v[(n + 1) % NSTACK];
            float mix = fmaf(push, vp, pop * vn);
            float pm = fmaxf(mix, 0.0f);
            if (fast5) {
                float p2 = pm * pm;
                pw[n] = (p2 * p2) * pm;
            } else {
                pw[n] = (pm > 0.f) ? powf(pm, sharp) : 0.f;
            }
        }
        float s01 = pw[0] + pw[1], s23 = pw[2] + pw[3], s45 = pw[4] + pw[5];
        float s67 = pw[6] + pw[7], s89 = pw[8] + pw[9], sab = pw[10] + pw[11];
        float S = ((s01 + s23) + (s45 + s67)) + (s89 + sab);
        float inv = __fdividef(1.0f, S + EPSV);
        #pragma unroll
        for (int n = 0; n < NSTACK; n++) v[n] = pw[n] * inv;
    }
    float* vf = g_vT + (size_t)T * NSTACK * BFIX + lane;
    #pragma unroll
    for (int n = 0; n < NSTACK; n++) vf[n * BFIX] = v[n];
}

// ---------------------------------------------------------------------------
// K5a: per-chunk products of a, computed in parallel from g_vT/g_popT.
// Same formula & same t-order as consumers -> bit-identical A.
// 3072 threads: idx = (ch*NSTACK + n)*BFIX + b  (coalesced over b).
// ---------------------------------------------------------------------------
__global__ void k5a_achunk() {
    int idx = blockIdx.x * blockDim.x + threadIdx.x;   // 0..3071
    int b = idx & (BFIX - 1);
    int rest = idx >> 5;
    int n = rest % NSTACK;
    int ch = rest / NSTACK;
    int np = (n + NSTACK - 1) % NSTACK;
    float A = 1.0f;
    int t0 = ch * CS;
    for (int j = 0; j < CS; j++) {
        int t = t0 + j;
        float pop = g_popT[t * BFIX + b];
        float push = 1.0f - pop;
        float vp = g_vT[((size_t)t * NSTACK + np) * BFIX + b];
        float vc = g_vT[((size_t)t * NSTACK + n) * BFIX + b];
        float c = push * vp;
        float a = 1.0f - (c + pop * vc);
        A *= a;
    }
    g_achunk[(b * NCH + ch) * NSTACK + n] = A;
}

// ---------------------------------------------------------------------------
// Staging helper: rebuild coef records for CS steps of batch b from g_vT/g_popT
// into s_c (layout [tl][CREC]).
// ---------------------------------------------------------------------------
template <bool WITH_Q>
__device__ __forceinline__ void stage_records(float* s_c, float* s_v, float* s_pp,
                                              int b, int t0) {
    int tid = threadIdx.x;
    for (int idx = tid; idx < (CS + 1) * NSTACK; idx += 256) {
        int tl = idx / NSTACK;
        int n = idx - tl * NSTACK;
        s_v[tl * NSTACK + n] = g_vT[((size_t)(t0 + tl) * NSTACK + n) * BFIX + b];
    }
    if (tid < CS) s_pp[tid] = g_popT[(t0 + tid) * BFIX + b];
    __syncthreads();
    for (int idx = tid; idx < CS * NSTACK; idx += 256) {
        int tl = idx / NSTACK;
        int n = idx - tl * NSTACK;
        float pop = s_pp[tl];
        float push = 1.0f - pop;
        float vp = s_v[tl * NSTACK + ((n + NSTACK - 1) % NSTACK)];
        float c = push * vp;
        float a = 1.0f - (c + pop * s_v[tl * NSTACK + n]);
        s_c[tl * CREC + n] = a;
        s_c[tl * CREC + 12 + n] = c;
        if (WITH_Q) s_c[tl * CREC + 24 + n] = s_v[(tl + 1) * NSTACK + n];
    }
    if (WITH_Q) {
        for (int tl = tid; tl < CS; tl += 256) {
            float sq = 0.f;
            #pragma unroll
            for (int n = 0; n < NSTACK; n++) sq += s_v[(tl + 1) * NSTACK + n];
            s_c[tl * CREC + 36] = s_pp[tl];
            s_c[tl * CREC + 37] = sq;
        }
    }
}

// ---------------------------------------------------------------------------
// K6 (pass 1): replay chunk in y-space from y=0 -> W, packed f32x2 slot pairs.
// grid (4, NCH-1, B), block 256.
// ---------------------------------------------------------------------------
__global__ void __launch_bounds__(256, 4)
k6_pass1(const float* __restrict__ x, int T, int V) {
    __shared__ __align__(16) float s_c[CS * CREC];
    __shared__ float s_v[(CS + 1) * NSTACK];
    __shared__ float s_pp[CS];
    int b = blockIdx.z, ch = blockIdx.y;
    int t0 = ch * CS;
    stage_records<false>(s_c, s_v, s_pp, b, t0);
    __syncthreads();

    int colf2 = blockIdx.x * blockDim.x + threadIdx.x;
    int s2 = V >> 1;
    const float2* xp = (const float2*)(x + (size_t)b * T * V) + (size_t)t0 * s2 + colf2;

    ull yx[6], yy[6];
    #pragma unroll
    for (int g = 0; g < 6; g++) { yx[g] = 0ull; yy[g] = 0ull; }

    float2 xbuf[4];
    #pragma unroll
    for (int j = 0; j < 4; j++) xbuf[j] = xp[(size_t)j * s2];

    for (int tt = 0; tt < CS; tt += 4) {
        #pragma unroll
        for (int j = 0; j < 4; j++) {
            int t = tt + j;
            float2 xv = xbuf[j];
            int tpre = (t + 4 < CS) ? t + 4 : CS - 1;
            xbuf[j] = xp[(size_t)tpre * s2];
            ull dupx = pack2(xv.x - ZEROOFF, xv.x - ZEROOFF);
            ull dupy = pack2(xv.y - ZEROOFF, xv.y - ZEROOFF);
            const ulonglong2* ap = (const ulonglong2*)(s_c + t * CREC);
            const ulonglong2* cp = (const ulonglong2*)(s_c + t * CREC + 12);
            #pragma unroll
            for (int h = 0; h < 3; h++) {
                ulonglong2 a2 = ap[h];
                ulonglong2 c2 = cp[h];
                yx[2 * h]     = fma2(a2.x, yx[2 * h],     mul2(c2.x, dupx));
                yx[2 * h + 1] = fma2(a2.y, yx[2 * h + 1], mul2(c2.y, dupx));
                yy[2 * h]     = fma2(a2.x, yy[2 * h],     mul2(c2.x, dupy));
                yy[2 * h + 1] = fma2(a2.y, yy[2 * h + 1], mul2(c2.y, dupy));
            }
        }
    }
    int col0 = colf2 * 2;
    ulonglong2* Wx = (ulonglong2*)(g_W + (((size_t)(b * NCH + ch)) * 2048 + col0) * NSTACK);
    ulonglong2* Wy = (ulonglong2*)(g_W + (((size_t)(b * NCH + ch)) * 2048 + col0 + 1) * NSTACK);
    #pragma unroll
    for (int h = 0; h < 3; h++) {
        ulonglong2 wx2; wx2.x = yx[2 * h]; wx2.y = yx[2 * h + 1];
        ulonglong2 wy2; wy2.x = yy[2 * h]; wy2.y = yy[2 * h + 1];
        Wx[h] = wx2;
        Wy[h] = wy2;
    }
}

// ---------------------------------------------------------------------------
// K8 (pass 2, fused combine): packed start-state fold + packed replay.
// grid (4, NCH, B), block 256.
// ---------------------------------------------------------------------------
__global__ void __launch_bounds__(256, 4)
k8_pass2(const float* __restrict__ x, float* __restrict__ outs,
         float* __restrict__ tops, int T, int V) {
    __shared__ __align__(16) float s_c[CS * CREC];
    __shared__ float s_v[(CS + 1) * NSTACK];
    __shared__ float s_pp[CS];
    __shared__ __align__(16) float sA[NCH - 1][NSTACK];
    int b = blockIdx.z, ch = blockIdx.y;
    int t0 = ch * CS;
    stage_records<true>(s_c, s_v, s_pp, b, t0);
    if (threadIdx.x < (NCH - 1) * NSTACK)
        sA[threadIdx.x / NSTACK][threadIdx.x % NSTACK] =
            g_achunk[b * NCH * NSTACK + threadIdx.x];
    __syncthreads();

    int colf2 = blockIdx.x * blockDim.x + threadIdx.x;
    int s2 = V >> 1;
    const float2* xp = (const float2*)(x + (size_t)b * T * V) + (size_t)t0 * s2 + colf2;
    float2* op = (float2*)(outs + (size_t)b * T * V) + (size_t)t0 * s2 + colf2;
    float2* tp = (float2*)(tops + (size_t)b * T * V) + (size_t)t0 * s2 + colf2;

    ull yx[6], yy[6];
    #pragma unroll
    for (int g = 0; g < 6; g++) { yx[g] = 0ull; yy[g] = 0ull; }

    int col0 = colf2 * 2;
    for (int j = 0; j < ch; j++) {
        const ulonglong2* Wx = (const ulonglong2*)(g_W + (((size_t)(b * NCH + j)) * 2048 + col0) * NSTACK);
        const ulonglong2* Wy = (const ulonglong2*)(g_W + (((size_t)(b * NCH + j)) * 2048 + col0 + 1) * NSTACK);
        const ulonglong2* Ap = (const ulonglong2*)&sA[j][0];
        #pragma unroll
        for (int h = 0; h < 3; h++) {
            ulonglong2 a2 = Ap[h];
            ulonglong2 wx2 = Wx[h];
            ulonglong2 wy2 = Wy[h];
            yx[2 * h]     = fma2(a2.x, yx[2 * h],     wx2.x);
            yx[2 * h + 1] = fma2(a2.y, yx[2 * h + 1], wx2.y);
            yy[2 * h]     = fma2(a2.x, yy[2 * h],     wy2.x);
            yy[2 * h + 1] = fma2(a2.y, yy[2 * h + 1], wy2.y);
        }
    }

    float2 xbuf[4];
    #pragma unroll
    for (int j = 0; j < 4; j++) xbuf[j] = xp[(size_t)j * s2];

    for (int tt = 0; tt < CS; tt += 4) {
        #pragma unroll
        for (int j = 0; j < 4; j++) {
            int t = tt + j;
            float2 xv = xbuf[j];
            int tpre = (t + 4 < CS) ? t + 4 : CS - 1;
            xbuf[j] = xp[(size_t)tpre * s2];
            ull dupx = pack2(xv.x - ZEROOFF, xv.x - ZEROOFF);
            ull dupy = pack2(xv.y - ZEROOFF, xv.y - ZEROOFF);
            const ulonglong2* ap = (const ulonglong2*)(s_c + t * CREC);
            const ulonglong2* cp = (const ulonglong2*)(s_c + t * CREC + 12);
            const ulonglong2* qp = (const ulonglong2*)(s_c + t * CREC + 24);
            ull taccx = 0ull, taccy = 0ull;
            #pragma unroll
            for (int h = 0; h < 3; h++) {
                ulonglong2 a2 = ap[h];
                ulonglong2 c2 = cp[h];
                ulonglong2 q2 = qp[h];
                yx[2 * h]     = fma2(a2.x, yx[2 * h],     mul2(c2.x, dupx));
                yx[2 * h + 1] = fma2(a2.y, yx[2 * h + 1], mul2(c2.y, dupx));
                yy[2 * h]     = fma2(a2.x, yy[2 * h],     mul2(c2.x, dupy));
                yy[2 * h + 1] = fma2(a2.y, yy[2 * h + 1], mul2(c2.y, dupy));
                taccx = fma2(yx[2 * h], q2.x, taccx);
                taccx = fma2(yx[2 * h + 1], q2.y, taccx);
                taccy = fma2(yy[2 * h], q2.x, taccy);
                taccy = fma2(yy[2 * h + 1], q2.y, taccy);
            }
            float tlx, thx, tly, thy;
            unpack2(taccx, tlx, thx);
            unpack2(taccy, tly, thy);
            float2 meta = *(const float2*)(s_c + t * CREC + 36);  // pop, sq
            float topx = fmaf(ZEROOFF, meta.y, tlx + thx);
            float topy = fmaf(ZEROOFF, meta.y, tly + thy);
            float2 o2; o2.x = meta.x * topx; o2.y = meta.x * topy;
            float2 t2; t2.x = topx; t2.y = topy;
            op[(size_t)t * s2] = o2;
            tp[(size_t)t * s2] = t2;
        }
    }
}

// ---------------------------------------------------------------------------
// Launch (7 kernels). Output layout: [outs BTV][latches BTV][pops BT][tops BTV]
// ---------------------------------------------------------------------------
extern "C" void kernel_launch(void* const* d_in, const int* in_sizes, int n_in,
                              void* d_out, int out_size) {
    const float* x = (const float*)d_in[0];
    const float* sp = (const float*)d_in[1];
    const float* shp = (const float*)d_in[2];
    const float* le = (const float*)d_in[3];
    const float* l0 = (const float*)d_in[4];

    int V = in_sizes[1];
    int B = in_sizes[4] / V;
    int T = in_sizes[0] / in_sizes[4];

    float* out = (float*)d_out;
    size_t btv = (size_t)B * T * V;
    float* outs = out;
    float* latches = out + btv;
    float* pops = out + 2 * btv;
    float* tops = out + 2 * btv + (size_t)B * T;

    k1_interp<<<B * T / 8, 256>>>(x, le, V);
    dim3 g2(KB2, B);
    k2_latch<<<g2, 128>>>(x, l0, sp, latches, T, V);
    k3b_pops<<<B * T / 256, 256>>>(pops, T);
    k4_scan<<<1, 32>>>(shp, T);
    k5a_achunk<<<12, 256>>>();
    dim3 g6(V / 512, NCH - 1, B);
    k6_pass1<<<g6, 256>>>(x, T, V);
    dim3 g8(V / 512, NCH, B);
    k8_pass2<<<g8, 256>>>(x, outs, tops, T, V);
}

// round 17
// speedup vs baseline: 1.0410x; 1.0410x over previous
#include <cuda_runtime.h>
#include <math.h>

#define NSTACK 12
#define ZEROOFF 0.001f
#define EPSV 1e-8f
#define CREC 40      // staged record: a[0:12] c[12:24] q[24:36] pop[36] sq[37] pad->40
#define KB2 8        // k2 blocks per batch
#define BFIX 32      // batch count (fixed shape)
#define TFIX 256     // time steps (fixed shape)

// Fixed shapes (B=32, T=256, V=2048).
__device__ float g_interp[32 * 256];
__device__ float g_partd[32 * KB2 * 256];
__device__ float g_partn[32 * KB2 * 256];
__device__ float g_partsp[KB2];
__device__ float g_popT[256 * 32];            // pops transposed [t][b]
__device__ float g_vT[257 * NSTACK * 32];     // pointer states [t][n][b], t=0..T

typedef unsigned long long ull;

__device__ __forceinline__ ull pack2(float lo, float hi) {
    ull r;
    asm("mov.b64 %0, {%1, %2};" : "=l"(r) : "f"(lo), "f"(hi));
    return r;
}
__device__ __forceinline__ void unpack2(ull v, float& lo, float& hi) {
    asm("mov.b64 {%0, %1}, %2;" : "=f"(lo), "=f"(hi) : "l"(v));
}
__device__ __forceinline__ ull fma2(ull a, ull b, ull c) {
    ull d;
    asm("fma.rn.f32x2 %0, %1, %2, %3;" : "=l"(d) : "l"(a), "l"(b), "l"(c));
    return d;
}
__device__ __forceinline__ ull mul2(ull a, ull b) {
    ull d;
    asm("mul.rn.f32x2 %0, %1, %2;" : "=l"(d) : "l"(a), "l"(b));
    return d;
}

// ---------------------------------------------------------------------------
// K1: interp[b,t] = cos(latch_enable, x[b,t]).  One WARP per row, MLP=8.
// ---------------------------------------------------------------------------
__global__ void k1_interp(const float* __restrict__ x, const float* __restrict__ le, int V) {
    int row = blockIdx.x * 8 + (threadIdx.x >> 5);
    int lane = threadIdx.x & 31;
    const float4* xp = (const float4*)(x + (size_t)row * V);
    const float4* le4 = (const float4*)le;
    float d = 0.f, n = 0.f, m = 0.f;
    for (int i0 = lane; i0 < V / 4; i0 += 128) {
        float4 xv[4], l[4];
        #pragma unroll
        for (int j = 0; j < 4; j++) { xv[j] = xp[i0 + 32 * j]; l[j] = le4[i0 + 32 * j]; }
        #pragma unroll
        for (int j = 0; j < 4; j++) {
            d += l[j].x * xv[j].x + l[j].y * xv[j].y + l[j].z * xv[j].z + l[j].w * xv[j].w;
            n += xv[j].x * xv[j].x + xv[j].y * xv[j].y + xv[j].z * xv[j].z + xv[j].w * xv[j].w;
            m += l[j].x * l[j].x + l[j].y * l[j].y + l[j].z * l[j].z + l[j].w * l[j].w;
        }
    }
    #pragma unroll
    for (int o = 16; o > 0; o >>= 1) {
        d += __shfl_xor_sync(0xffffffffu, d, o);
        n += __shfl_xor_sync(0xffffffffu, n, o);
        m += __shfl_xor_sync(0xffffffffu, m, o);
    }
    if (lane == 0) {
        float nle = fmaxf(sqrtf(m), EPSV);
        float nx = fmaxf(sqrtf(n), EPSV);
        g_interp[row] = d / (nle * nx);
    }
}

// ---------------------------------------------------------------------------
// K2: latch scan + fused pop partials. grid (KB2, B), block 128, float2/thread.
// ---------------------------------------------------------------------------
__global__ void k2_latch(const float* __restrict__ x, const float* __restrict__ latch0,
                         const float* __restrict__ sp, float* __restrict__ latches,
                         int T, int V) {
    __shared__ float s_i[256];
    __shared__ float s_wd[256][4];
    __shared__ float s_wn[256][4];
    __shared__ float s_sp[4];
    int b = blockIdx.y;
    int tid = threadIdx.x;
    int lane = tid & 31;
    int w = tid >> 5;
    int v2 = blockIdx.x * blockDim.x + tid;
    int stride2 = V >> 1;

    for (int t = tid; t < T; t += blockDim.x) s_i[t] = g_interp[b * T + t];
    __syncthreads();

    float2 sp2 = ((const float2*)sp)[v2];
    float2 latch = ((const float2*)(latch0 + (size_t)b * V))[v2];
    const float2* xp = (const float2*)(x + (size_t)b * T * V) + v2;
    float2* lp = (float2*)(latches + (size_t)b * T * V) + v2;

    {
        float d = sp2.x * latch.x + sp2.y * latch.y;
        float n = latch.x * latch.x + latch.y * latch.y;
        float m = sp2.x * sp2.x + sp2.y * sp2.y;
        #pragma unroll
        for (int o = 16; o > 0; o >>= 1) {
            d += __shfl_xor_sync(0xffffffffu, d, o);
            n += __shfl_xor_sync(0xffffffffu, n, o);
            m += __shfl_xor_sync(0xffffffffu, m, o);
        }
        if (lane == 0) { s_wd[0][w] = d; s_wn[0][w] = n; s_sp[w] = m; }
    }

    for (int t0 = 0; t0 < T; t0 += 8) {
        float2 xs[8];
        #pragma unroll
        for (int j = 0; j < 8; j++) xs[j] = xp[(size_t)(t0 + j) * stride2];
        float d8[8], n8[8];
        #pragma unroll
        for (int j = 0; j < 8; j++) {
            float i = s_i[t0 + j];
            latch.x = fmaf(i, xs[j].x - latch.x, latch.x);
            latch.y = fmaf(i, xs[j].y - latch.y, latch.y);
            lp[(size_t)(t0 + j) * stride2] = latch;
            d8[j] = sp2.x * latch.x + sp2.y * latch.y;
            n8[j] = latch.x * latch.x + latch.y * latch.y;
        }
        #pragma unroll
        for (int o = 16; o > 0; o >>= 1) {
            #pragma unroll
            for (int j = 0; j < 8; j++) {
                d8[j] += __shfl_xor_sync(0xffffffffu, d8[j], o);
                n8[j] += __shfl_xor_sync(0xffffffffu, n8[j], o);
            }
        }
        if (lane == 0) {
            #pragma unroll
            for (int j = 0; j < 8; j++) {
                int t = t0 + j;
                if (t + 1 < T) { s_wd[t + 1][w] = d8[j]; s_wn[t + 1][w] = n8[j]; }
            }
        }
    }
    __syncthreads();
    int pbase = (b * KB2 + blockIdx.x) * T;
    for (int t = tid; t < T; t += blockDim.x) {
        g_partd[pbase + t] = s_wd[t][0] + s_wd[t][1] + s_wd[t][2] + s_wd[t][3];
        g_partn[pbase + t] = s_wn[t][0] + s_wn[t][1] + s_wn[t][2] + s_wn[t][3];
    }
    if (b == 0 && tid == 0)
        g_partsp[blockIdx.x] = s_sp[0] + s_sp[1] + s_sp[2] + s_sp[3];
}

// ---------------------------------------------------------------------------
// K3b: finalize pop[b,t] = elu(cos); write pops output + transposed copy.
// ---------------------------------------------------------------------------
__global__ void k3b_pops(float* __restrict__ pops, int T) {
    int bt = blockIdx.x * blockDim.x + threadIdx.x;
    int b = bt / T;
    int t = bt - b * T;
    float d = 0.f, n = 0.f;
    #pragma unroll
    for (int blk = 0; blk < KB2; blk++) {
        d += g_partd[(b * KB2 + blk) * T + t];
        n += g_partn[(b * KB2 + blk) * T + t];
    }
    float sp2 = 0.f;
    #pragma unroll
    for (int blk = 0; blk < KB2; blk++) sp2 += g_partsp[blk];
    float nsp = fmaxf(sqrtf(sp2), EPSV);
    float nl = fmaxf(sqrtf(n), EPSV);
    float c = d / (nsp * nl);
    float p = (c > 0.0f) ? c : expm1f(c);
    pops[bt] = p;
    g_popT[t * BFIX + b] = p;
}

// ---------------------------------------------------------------------------
// K4: pointer scan, lane-per-batch, stores ONLY the pointer state v.
// One warp, all 32 batches, no cross-lane ops.
// ---------------------------------------------------------------------------
__global__ void k4_scan(const float* __restrict__ sharp_ptr, int T) {
    __shared__ float s_pop[256 * BFIX];   // [t][b], 32KB
    int lane = threadIdx.x;               // = batch b

    {
        const float4* src = (const float4*)g_popT;
        float4* dst = (float4*)s_pop;
        for (int i = lane; i < T * BFIX / 4; i += 32) dst[i] = src[i];
    }
    __syncwarp();

    float sharp = sharp_ptr[0];
    bool fast5 = (sharp == 5.0f);

    float v[NSTACK];
    #pragma unroll
    for (int n = 0; n < NSTACK; n++) v[n] = 0.f;
    v[0] = 1.0f;

    for (int t = 0; t < T; t++) {
        float* vf = g_vT + (size_t)t * NSTACK * BFIX + lane;
        #pragma unroll
        for (int n = 0; n < NSTACK; n++) vf[n * BFIX] = v[n];

        float pop = s_pop[t * BFIX + lane];
        float push = 1.0f - pop;

        float pw[NSTACK];
        #pragma unroll
        for (int n = 0; n < NSTACK; n++) {
            float vp = v[(n + NSTACK - 1) % NSTACK];
            float vn = v[(n + 1) % NSTACK];
            float mix = fmaf(push, vp, pop * vn);
            float pm = fmaxf(mix, 0.0f);
            if (fast5) {
                float p2 = pm * pm;
                pw[n] = (p2 * p2) * pm;
            } else {
                pw[n] = (pm > 0.f) ? powf(pm, sharp) : 0.f;
            }
        }
        float s01 = pw[0] + pw[1], s23 = pw[2] + pw[3], s45 = pw[4] + pw[5];
        float s67 = pw[6] + pw[7], s89 = pw[8] + pw[9], sab = pw[10] + pw[11];
        float S = ((s01 + s23) + (s45 + s67)) + (s89 + sab);
        float inv = __fdividef(1.0f, S + EPSV);
        #pragma unroll
        for (int n = 0; n < NSTACK; n++) v[n] = pw[n] * inv;
    }
    float* vf = g_vT + (size_t)T * NSTACK * BFIX + lane;
    #pragma unroll
    for (int n = 0; n < NSTACK; n++) vf[n * BFIX] = v[n];
}

// ---------------------------------------------------------------------------
// K9: full-T stack scan (replaces k6/k5a/k8). grid (V/256, B), block 128.
// All 256 coef records reconstructed into 40KB dynamic smem up-front
// (no in-loop syncs), x prefetch ring depth 4, packed f32x2 math.
// ---------------------------------------------------------------------------
__global__ void __launch_bounds__(128)
k9_scan(const float* __restrict__ x, float* __restrict__ outs,
        float* __restrict__ tops, int T, int V) {
    extern __shared__ __align__(16) float s_c[];   // TFIX * CREC = 40KB
    __shared__ float s_v[(TFIX + 1) * NSTACK];     // 12.3KB
    __shared__ float s_pp[TFIX];                   // 1KB
    int b = blockIdx.y;
    int tid = threadIdx.x;

    // stage: v states + pops
    for (int idx = tid; idx < (TFIX + 1) * NSTACK; idx += 128)
        s_v[idx] = g_vT[(size_t)idx * BFIX + b];
    for (int t = tid; t < TFIX; t += 128) s_pp[t] = g_popT[t * BFIX + b];
    __syncthreads();
    // stage: reconstruct records
    for (int idx = tid; idx < TFIX * NSTACK; idx += 128) {
        int tl = idx / NSTACK;
        int n = idx - tl * NSTACK;
        float pop = s_pp[tl];
        float push = 1.0f - pop;
        float vp = s_v[tl * NSTACK + ((n + NSTACK - 1) % NSTACK)];
        float c = push * vp;
        float a = 1.0f - (c + pop * s_v[tl * NSTACK + n]);
        s_c[tl * CREC + n] = a;
        s_c[tl * CREC + 12 + n] = c;
        s_c[tl * CREC + 24 + n] = s_v[(tl + 1) * NSTACK + n];
    }
    for (int tl = tid; tl < TFIX; tl += 128) {
        float sq = 0.f;
        #pragma unroll
        for (int n = 0; n < NSTACK; n++) sq += s_v[(tl + 1) * NSTACK + n];
        s_c[tl * CREC + 36] = s_pp[tl];
        s_c[tl * CREC + 37] = sq;
    }
    __syncthreads();

    int colf2 = blockIdx.x * blockDim.x + tid;     // float2 column
    int s2 = V >> 1;
    const float2* xp = (const float2*)(x + (size_t)b * T * V) + colf2;
    float2* op = (float2*)(outs + (size_t)b * T * V) + colf2;
    float2* tp = (float2*)(tops + (size_t)b * T * V) + colf2;

    ull yx[6], yy[6];
    #pragma unroll
    for (int g = 0; g < 6; g++) { yx[g] = 0ull; yy[g] = 0ull; }

    float2 xbuf[4];
    #pragma unroll
    for (int j = 0; j < 4; j++) xbuf[j] = xp[(size_t)j * s2];

    for (int tt = 0; tt < TFIX; tt += 4) {
        #pragma unroll
        for (int j = 0; j < 4; j++) {
            int t = tt + j;
            float2 xv = xbuf[j];
            int tpre = (t + 4 < TFIX) ? t + 4 : TFIX - 1;
            xbuf[j] = xp[(size_t)tpre * s2];
            ull dupx = pack2(xv.x - ZEROOFF, xv.x - ZEROOFF);
            ull dupy = pack2(xv.y - ZEROOFF, xv.y - ZEROOFF);
            const ulonglong2* ap = (const ulonglong2*)(s_c + t * CREC);
            const ulonglong2* cp = (const ulonglong2*)(s_c + t * CREC + 12);
            const ulonglong2* qp = (const ulonglong2*)(s_c + t * CREC + 24);
            ull taccx = 0ull, taccy = 0ull;
            #pragma unroll
            for (int h = 0; h < 3; h++) {
                ulonglong2 a2 = ap[h];
                ulonglong2 c2 = cp[h];
                ulonglong2 q2 = qp[h];
                yx[2 * h]     = fma2(a2.x, yx[2 * h],     mul2(c2.x, dupx));
                yx[2 * h + 1] = fma2(a2.y, yx[2 * h + 1], mul2(c2.y, dupx));
                yy[2 * h]     = fma2(a2.x, yy[2 * h],     mul2(c2.x, dupy));
                yy[2 * h + 1] = fma2(a2.y, yy[2 * h + 1], mul2(c2.y, dupy));
                taccx = fma2(yx[2 * h], q2.x, taccx);
                taccx = fma2(yx[2 * h + 1], q2.y, taccx);
                taccy = fma2(yy[2 * h], q2.x, taccy);
                taccy = fma2(yy[2 * h + 1], q2.y, taccy);
            }
            float tlx, thx, tly, thy;
            unpack2(taccx, tlx, thx);
            unpack2(taccy, tly, thy);
            float2 meta = *(const float2*)(s_c + t * CREC + 36);  // pop, sq
            float topx = fmaf(ZEROOFF, meta.y, tlx + thx);
            float topy = fmaf(ZEROOFF, meta.y, tly + thy);
            float2 o2; o2.x = meta.x * topx; o2.y = meta.x * topy;
            float2 t2; t2.x = topx; t2.y = topy;
            op[(size_t)t * s2] = o2;
            tp[(size_t)t * s2] = t2;
        }
    }
}

// ---------------------------------------------------------------------------
// Launch (5 kernels). Output layout: [outs BTV][latches BTV][pops BT][tops BTV]
// ---------------------------------------------------------------------------
extern "C" void kernel_launch(void* const* d_in, const int* in_sizes, int n_in,
                              void* d_out, int out_size) {
    const float* x = (const float*)d_in[0];
    const float* sp = (const float*)d_in[1];
    const float* shp = (const float*)d_in[2];
    const float* le = (const float*)d_in[3];
    const float* l0 = (const float*)d_in[4];

    int V = in_sizes[1];
    int B = in_sizes[4] / V;
    int T = in_sizes[0] / in_sizes[4];

    float* out = (float*)d_out;
    size_t btv = (size_t)B * T * V;
    float* outs = out;
    float* latches = out + btv;
    float* pops = out + 2 * btv;
    float* tops = out + 2 * btv + (size_t)B * T;

    // k9 needs 40KB dynamic smem (above the 48KB-combined default).
    static bool attr_set = false;
    if (!attr_set) {
        cudaFuncSetAttribute(k9_scan, cudaFuncAttributeMaxDynamicSharedMemorySize,
                             TFIX * CREC * (int)sizeof(float));
        attr_set = true;
    }

    k1_interp<<<B * T / 8, 256>>>(x, le, V);
    dim3 g2(KB2, B);
    k2_latch<<<g2, 128>>>(x, l0, sp, latches, T, V);
    k3b_pops<<<B * T / 256, 256>>>(pops, T);
    k4_scan<<<1, 32>>>(shp, T);
    dim3 g9(V / 256, B);
    k9_scan<<<g9, 128, TFIX * CREC * sizeof(float)>>>(x, outs, tops, T, V);
}